// round 15
// baseline (speedup 1.0000x reference)
#include <cuda_runtime.h>
#include <cuda_fp16.h>
#include <cstdint>

// VectorQuantizer via mma.sync (HMMA fp16, fp32 accum) pre-filter + exact
// fp32-chain verification. Single-pass capture: warp-row min known immediately;
// capture vs min(warpmin, partial rowmin)+eps is a provable superset of true
// candidates; verify re-filters vs the final rowmin and reproduces the
// R3-validated reference rounding (sequential fmaf dot chain d-ascending,
// mul-then-add norms, d = fl(fl(xn-2m)+en), first-index tie-break) => bitwise
// identical argmin. out = q; loss = 1.25*mean(d_min).

#define DDIM 64
#define KCODES 512
#define ROWS_TILE 128
#define NTHREADS 512
#define CAP 24
#define MAXG 256
#define AS 36                  // A row stride in u32 words (72 f16); 144B rows
#define XSS 68                 // xs row stride in floats

typedef unsigned int u32;

__device__ float  g_embT[KCODES * DDIM];   // [code][d] fp32 exact copy
__device__ double g_partial[MAXG];
__device__ unsigned g_count;               // zero-init; last block resets

struct SMT {
    double lossw[16];
    double red[MAXG];
    u32    A[ROWS_TILE * AS];              // f16x2 staged x tile
    float  xs[ROWS_TILE * XSS];            // fp32 staged x tile (verify)
    float  ens[KCODES];                    // exact ||e_k||^2 (ref chain)
    u32    rowmin[ROWS_TILE];              // shifted-score fp32 bits (positive)
    int    ccnt[ROWS_TILE];
    int    codes[2][ROWS_TILE];            // ping-pong (write hidden in MMA)
    float  cscore[ROWS_TILE * CAP];        // captured shifted scores
    unsigned short ccode[ROWS_TILE * CAP];
    float  epsv;
    int    flag;
};

__device__ __forceinline__ u32 smem_u32(const void* p) {
    u32 a;
    asm("{ .reg .u64 t; cvta.to.shared.u64 t, %1; cvt.u32.u64 %0, t; }"
        : "=r"(a) : "l"(p));
    return a;
}
__device__ __forceinline__ void mma16816(float* c, const u32* a, const u32* b) {
    asm volatile(
        "mma.sync.aligned.m16n8k16.row.col.f32.f16.f16.f32 "
        "{%0,%1,%2,%3},{%4,%5,%6,%7},{%8,%9},{%0,%1,%2,%3};\n"
        : "+f"(c[0]), "+f"(c[1]), "+f"(c[2]), "+f"(c[3])
        : "r"(a[0]), "r"(a[1]), "r"(a[2]), "r"(a[3]), "r"(b[0]), "r"(b[1]));
}
__device__ __forceinline__ void ldsm4(u32& a0, u32& a1, u32& a2, u32& a3, u32 addr) {
    asm volatile("ldmatrix.sync.aligned.m8n8.x4.shared.b16 {%0,%1,%2,%3}, [%4];"
                 : "=r"(a0), "=r"(a1), "=r"(a2), "=r"(a3) : "r"(addr));
}

// stage one float4 (quad q of row-major x tile) into fp16 A and fp32 xs
__device__ __forceinline__ void stageX(SMT* smp, int q, float4 v) {
    int row = q >> 4, quad = q & 15;
    __half2 h0 = __floats2half2_rn(v.x, v.y);
    __half2 h1 = __floats2half2_rn(v.z, v.w);
    uint2 u;
    u.x = *(u32*)&h0;
    u.y = *(u32*)&h1;
    *(uint2*)&smp->A[row * AS + quad * 2] = u;
    *(float4*)&smp->xs[row * XSS + quad * 4] = v;
}

// ---------------- prep: exact transpose emb[d][k] -> g_embT[k][d] ----------------
__global__ void vq_prep(const float* __restrict__ emb)
{
    int i = blockIdx.x * blockDim.x + threadIdx.x;   // 32768
    int d = i >> 9, k = i & 511;
    g_embT[k * DDIM + d] = emb[i];
}

// ---------------- main ----------------
__global__ __launch_bounds__(NTHREADS, 1)
void vq_main(const float* __restrict__ x, const float* __restrict__ emb,
             float* __restrict__ out, int ntiles, long nelem, int writeLoss)
{
    extern __shared__ char smraw[];
    SMT* smp = (SMT*)smraw;

    const int t    = threadIdx.x;
    const int lane = t & 31;
    const int warp = t >> 5;
    const int gid  = lane >> 2;
    const int tig  = lane & 3;
    const int cgbase = warp * 32;    // this warp's 32 codes
    const int stride = gridDim.x;

    // ldmatrix lane geometry: mat = lane>>3; rows (mat&1)*8+(lane&7); kcol (mat>>1)*4
    const int matid  = lane >> 3;
    const int rowoff = ((matid & 1) << 3) + (lane & 7);
    const int kcolw  = (matid >> 1) << 2;
    const u32 Au32   = smem_u32(smp->A);

    // ---- exact ||e_k||^2 (reference chain) ----
    {
        float s = 0.f;
        #pragma unroll
        for (int d = 0; d < DDIM; d++) {
            float e = emb[d * KCODES + t];
            s = __fadd_rn(s, __fmul_rn(e, e));
        }
        smp->ens[t] = s;
    }
    if (t < ROWS_TILE) { smp->ccnt[t] = 0; smp->rowmin[t] = 0x7f800000u; }
    __syncthreads();

    // ---- eps from emax: 2E <= 2^-9*||x||*emax (||x||<=16) x2 safety ----
    {
        float mx = smp->ens[t];
        #pragma unroll
        for (int ofs = 16; ofs > 0; ofs >>= 1)
            mx = fmaxf(mx, __shfl_xor_sync(0xffffffffu, mx, ofs));
        float* redf = (float*)smp->red;
        if (lane == 0) redf[warp] = mx;
        __syncthreads();
        if (t == 0) {
            float m2 = redf[0];
            for (int i = 1; i < 16; i++) m2 = fmaxf(m2, redf[i]);
            smp->epsv = 0.0625f * sqrtf(m2) + 1e-3f;
        }
    }

    // ---- loop-invariant B fragments + shifted norms ----
    u32 B[4][4][2];
    float enc[8];
    #pragma unroll
    for (int nt = 0; nt < 4; nt++) {
        int codeB = cgbase + nt * 8 + gid;
        #pragma unroll
        for (int kk = 0; kk < 4; kk++) {
            int k0 = kk * 16 + 2 * tig;
            __half2 l0 = __floats2half2_rn(emb[k0 * KCODES + codeB],
                                           emb[(k0 + 1) * KCODES + codeB]);
            __half2 l1 = __floats2half2_rn(emb[(k0 + 8) * KCODES + codeB],
                                           emb[(k0 + 9) * KCODES + codeB]);
            B[nt][kk][0] = *(u32*)&l0;
            B[nt][kk][1] = *(u32*)&l1;
        }
        int c0 = cgbase + nt * 8 + 2 * tig;
        enc[nt * 2 + 0] = smp->ens[c0] + 512.0f;     // shift -> scores positive
        enc[nt * 2 + 1] = smp->ens[c0 + 1] + 512.0f;
    }

    long tile = blockIdx.x;

    if (tile < ntiles) {
        const float4* xp = (const float4*)(x + tile * (ROWS_TILE * DDIM));
        #pragma unroll
        for (int i = 0; i < 4; i++) stageX(smp, t + i * NTHREADS, xp[t + i * NTHREADS]);
    }
    __syncthreads();

    double lossacc = 0.0;
    volatile u32* vrowmin = smp->rowmin;
    int  par = 0, prevPar = 0;
    long prevObase = 0;
    bool prevValid = false;

    for (; tile < ntiles; tile += stride) {
        long nxt = tile + stride;
        bool has = nxt < ntiles;
        const float eps = smp->epsv;
        float4 pf[4];
        const int* pcodes = smp->codes[prevPar];

        // ======== phase 1: MMA sweep + capture; hide prev-write + prefetch ========
        #pragma unroll 1
        for (int s = 0; s < 8; s++) {
            const int mt = (s + warp) & 7;
            const int rA = mt * 16 + gid;
            u32 abase = Au32 + (u32)(((mt * 16 + rowoff) * AS + kcolw) << 2);
            u32 a[4][4];
            #pragma unroll
            for (int kk = 0; kk < 4; kk++)
                ldsm4(a[kk][0], a[kk][1], a[kk][2], a[kk][3], abase + (kk << 5));

            float acc[4][4];
            #pragma unroll
            for (int nt = 0; nt < 4; nt++)
                #pragma unroll
                for (int j = 0; j < 4; j++) acc[nt][j] = 0.f;
            #pragma unroll
            for (int nt = 0; nt < 4; nt++)
                #pragma unroll
                for (int kk = 0; kk < 4; kk++)
                    mma16816(acc[nt], a[kk], B[nt][kk]);

            // shifted scores s = (en+512) - 2*m  (positive)
            float sA[8], sB[8];
            #pragma unroll
            for (int nt = 0; nt < 4; nt++) {
                sA[nt * 2 + 0] = fmaf(-2.f, acc[nt][0], enc[nt * 2 + 0]);
                sA[nt * 2 + 1] = fmaf(-2.f, acc[nt][1], enc[nt * 2 + 1]);
                sB[nt * 2 + 0] = fmaf(-2.f, acc[nt][2], enc[nt * 2 + 0]);
                sB[nt * 2 + 1] = fmaf(-2.f, acc[nt][3], enc[nt * 2 + 1]);
            }

            float mA = sA[0], mB = sB[0];
            #pragma unroll
            for (int j = 1; j < 8; j++) {
                mA = fminf(mA, sA[j]);
                mB = fminf(mB, sB[j]);
            }
            mA = fminf(mA, __shfl_xor_sync(0xffffffffu, mA, 1));
            mA = fminf(mA, __shfl_xor_sync(0xffffffffu, mA, 2));
            mB = fminf(mB, __shfl_xor_sync(0xffffffffu, mB, 1));
            mB = fminf(mB, __shfl_xor_sync(0xffffffffu, mB, 2));
            if (tig == 0) {
                atomicMin(&smp->rowmin[rA],     __float_as_uint(mA));
                atomicMin(&smp->rowmin[rA + 8], __float_as_uint(mB));
            }

            float TA = fminf(mA, __uint_as_float(vrowmin[rA]))     + eps;
            float TB = fminf(mB, __uint_as_float(vrowmin[rA + 8])) + eps;
            #pragma unroll
            for (int j = 0; j < 8; j++) {
                int code = cgbase + (j >> 1) * 8 + 2 * tig + (j & 1);
                if (sA[j] <= TA) {
                    int i2 = atomicAdd(&smp->ccnt[rA], 1);
                    if (i2 < CAP) {
                        smp->cscore[rA * CAP + i2] = sA[j];
                        smp->ccode[rA * CAP + i2]  = (unsigned short)code;
                    }
                }
                if (sB[j] <= TB) {
                    int i2 = atomicAdd(&smp->ccnt[rA + 8], 1);
                    if (i2 < CAP) {
                        smp->cscore[(rA + 8) * CAP + i2] = sB[j];
                        smp->ccode[(rA + 8) * CAP + i2]  = (unsigned short)code;
                    }
                }
            }

            if (s < 4) {
                if (has) {
                    const float4* xp = (const float4*)(x + nxt * (ROWS_TILE * DDIM));
                    pf[s] = __ldcs(&xp[t + s * NTHREADS]);
                }
                if (prevValid) {
                    int q = s * NTHREADS + t;
                    float4* o4 = (float4*)(out + prevObase);
                    const float4* e4 = (const float4*)g_embT;
                    o4[q] = e4[pcodes[q >> 4] * 16 + (q & 15)];
                }
            }
        }
        __syncthreads();   // mins/captures final; prev write done

        // ======== phase 2: exact verify (xn by sub0 || dots by subs 1-3) ========
        {
            const int r = t >> 2, sub = t & 3;
            const int lbase = lane & ~3;
            const float* xrow = &smp->xs[r * XSS];
            int   cnt  = smp->ccnt[r];
            float gthr = __uint_as_float(smp->rowmin[r]) + eps;
            bool  ok   = (cnt <= CAP);
            float bd = 3.402823466e38f;
            int   bk = KCODES;

            float xn = 0.f;
            if (sub == 0) {        // exact ||x||^2 chain (once per row)
                #pragma unroll
                for (int d = 0; d < DDIM; d++)
                    xn = __fadd_rn(xn, __fmul_rn(xrow[d], xrow[d]));
            }

            float mv[8]; int kv[8]; int nm = 0;
            if (ok && sub != 0) {
                for (int ci = sub - 1; ci < cnt; ci += 3)
                    if (smp->cscore[r * CAP + ci] <= gthr && nm < 8)
                        kv[nm++] = smp->ccode[r * CAP + ci];
                int i = 0;
                for (; i + 1 < nm; i += 2) {   // ILP-2 exact chains
                    const float2* e1 = (const float2*)(g_embT + kv[i] * DDIM);
                    const float2* e2 = (const float2*)(g_embT + kv[i + 1] * DDIM);
                    float m1 = 0.f, m2 = 0.f;
                    #pragma unroll
                    for (int d2 = 0; d2 < 32; d2++) {
                        float2 xa = *(const float2*)&xrow[2 * d2];
                        float2 ea = e1[d2], eb = e2[d2];
                        m1 = fmaf(xa.x, ea.x, m1); m1 = fmaf(xa.y, ea.y, m1);
                        m2 = fmaf(xa.x, eb.x, m2); m2 = fmaf(xa.y, eb.y, m2);
                    }
                    mv[i] = m1; mv[i + 1] = m2;
                }
                if (i < nm) {
                    const float2* e1 = (const float2*)(g_embT + kv[i] * DDIM);
                    float m1 = 0.f;
                    #pragma unroll
                    for (int d2 = 0; d2 < 32; d2++) {
                        float2 xa = *(const float2*)&xrow[2 * d2];
                        float2 ea = e1[d2];
                        m1 = fmaf(xa.x, ea.x, m1); m1 = fmaf(xa.y, ea.y, m1);
                    }
                    mv[i] = m1;
                }
            }

            xn = __shfl_sync(0xffffffffu, xn, lbase);   // broadcast from sub0
            if (ok && xn <= 256.0f) {
                for (int i = 0; i < nm; i++) {
                    int k = kv[i];
                    float dd = __fadd_rn(__fsub_rn(xn, 2.0f * mv[i]), smp->ens[k]);
                    if (dd < bd || (dd == bd && k < bk)) { bd = dd; bk = k; }
                }
            } else {
                // rare fallback: full exact scan (lexicographic combine below)
                bd = 3.402823466e38f; bk = KCODES;
                for (int k = sub; k < KCODES; k += 4) {
                    const float* e = g_embT + k * DDIM;
                    float m = 0.f;
                    #pragma unroll
                    for (int d = 0; d < DDIM; d++) m = fmaf(xrow[d], e[d], m);
                    float dd = __fadd_rn(__fsub_rn(xn, 2.0f * m), smp->ens[k]);
                    if (dd < bd || (dd == bd && k < bk)) { bd = dd; bk = k; }
                }
            }
            #pragma unroll
            for (int ofs = 1; ofs <= 2; ofs <<= 1) {   // lexicographic (d,k)
                float od = __shfl_xor_sync(0xffffffffu, bd, ofs);
                int   ok2 = __shfl_xor_sync(0xffffffffu, bk, ofs);
                if (od < bd || (od == bd && ok2 < bk)) { bd = od; bk = ok2; }
            }
            if (sub == 0) {
                smp->codes[par][r] = bk;
                lossacc += (double)bd;
                smp->ccnt[r] = 0;
                smp->rowmin[r] = 0x7f800000u;
            }
        }
        __syncthreads();   // codes ready; resets done; A free

        // ======== phase 3: stage next tile ========
        if (has) {
            #pragma unroll
            for (int i = 0; i < 4; i++) stageX(smp, t + i * NTHREADS, pf[i]);
        }
        __syncthreads();

        prevObase = tile * (ROWS_TILE * DDIM);
        prevPar = par;
        prevValid = true;
        par ^= 1;
    }

    // ---- drain: write last tile ----
    if (prevValid) {
        const int* pcodes = smp->codes[prevPar];
        float4* o4 = (float4*)(out + prevObase);
        const float4* e4 = (const float4*)g_embT;
        #pragma unroll
        for (int rep = 0; rep < 4; rep++) {
            int q = rep * NTHREADS + t;
            o4[q] = e4[pcodes[q >> 4] * 16 + (q & 15)];
        }
    }

    // ---- loss: deterministic reduce ----
    {
        double v = lossacc;
        #pragma unroll
        for (int ofs = 16; ofs > 0; ofs >>= 1)
            v += __shfl_xor_sync(0xffffffffu, v, ofs);
        if (lane == 0) smp->lossw[warp] = v;
    }
    __syncthreads();
    if (t == 0) {
        double s = 0.0;
        for (int i = 0; i < 16; i++) s += smp->lossw[i];
        g_partial[blockIdx.x] = s;
        __threadfence();
        unsigned old = atomicAdd(&g_count, 1u);
        smp->flag = (old == gridDim.x - 1) ? 1 : 0;
    }
    __syncthreads();
    if (smp->flag) {
        volatile double* gp = g_partial;
        if (t < MAXG) smp->red[t] = (t < (int)gridDim.x) ? gp[t] : 0.0;
        __syncthreads();
        #pragma unroll
        for (int ofs = 128; ofs > 0; ofs >>= 1) {
            if (t < ofs) smp->red[t] += smp->red[t + ofs];
            __syncthreads();
        }
        if (t == 0) {
            if (writeLoss) out[nelem] = (float)(smp->red[0] * 1.25 / (double)nelem);
            g_count = 0;   // reset for next launch / graph replay
        }
    }
}

extern "C" void kernel_launch(void* const* d_in, const int* in_sizes, int n_in,
                              void* d_out, int out_size)
{
    const float* x   = (const float*)d_in[0];
    const float* emb = (const float*)d_in[1];
    float* out = (float*)d_out;

    long n      = (long)in_sizes[0];              // 8388608
    int  ntiles = (int)(n / (DDIM * ROWS_TILE));  // 1024

    static int nsm = 0;
    if (nsm == 0) {
        cudaDeviceGetAttribute(&nsm, cudaDevAttrMultiProcessorCount, 0);
        if (nsm <= 0) nsm = 148;
    }
    int grid = nsm;
    if (grid > MAXG) grid = MAXG;
    if (grid > ntiles) grid = ntiles;

    size_t smem = sizeof(SMT);                    // ~80 KB
    cudaFuncSetAttribute(vq_main, cudaFuncAttributeMaxDynamicSharedMemorySize, (int)smem);

    int writeLoss = ((long)out_size > n) ? 1 : 0;

    vq_prep<<<(DDIM * KCODES) / NTHREADS, NTHREADS>>>(emb);
    vq_main<<<grid, NTHREADS, smem>>>(x, emb, out, ntiles, n, writeLoss);
}